// round 16
// baseline (speedup 1.0000x reference)
#include <cuda_runtime.h>
#include <cuda_fp16.h>
#include <cstdint>

#define DEV_INLINE __device__ __forceinline__

constexpr int NN = 8192;   // nodes
constexpr int DF = 256;    // feature dim
constexpr float YSCALE = 4096.f;   // exact pow2: keeps Y out of fp16 subnormals

// ---------------- intermediates (static device globals; no runtime alloc) ----
__device__ float  g_inv_deg[NN];
__device__ __half g_Ah[(size_t)NN * NN];     // fp16 copy of adjacency (rn)
__device__ __half g_ysTh[(size_t)DF * NN];   // [d][j] = fp16( YSCALE*inv_j*(xW)[j][d] )

// ============================================================================
// helpers (baseline sm_103 ISA only: cp.async, ldmatrix, mma.sync)
// ============================================================================
DEV_INLINE uint32_t smem_u32(const void* p) {
    uint32_t a;
    asm("{ .reg .u64 t; cvta.to.shared.u64 t, %1; cvt.u32.u64 %0, t; }" : "=r"(a) : "l"(p));
    return a;
}
DEV_INLINE void cp16(uint32_t saddr, const void* g) {
    asm volatile("cp.async.cg.shared.global [%0], [%1], 16;" :: "r"(saddr), "l"(g));
}
DEV_INLINE void cp_commit() { asm volatile("cp.async.commit_group;"); }
template <int N> DEV_INLINE void cp_wait() { asm volatile("cp.async.wait_group %0;" :: "n"(N)); }

DEV_INLINE void ldsm4(uint32_t* d, uint32_t addr) {
    asm volatile("ldmatrix.sync.aligned.m8n8.x4.shared.b16 {%0,%1,%2,%3}, [%4];"
                 : "=r"(d[0]), "=r"(d[1]), "=r"(d[2]), "=r"(d[3]) : "r"(addr));
}
DEV_INLINE void ldsm4t(uint32_t* d, uint32_t addr) {
    asm volatile("ldmatrix.sync.aligned.m8n8.x4.trans.shared.b16 {%0,%1,%2,%3}, [%4];"
                 : "=r"(d[0]), "=r"(d[1]), "=r"(d[2]), "=r"(d[3]) : "r"(addr));
}
DEV_INLINE void mma_f16(float* c, const uint32_t* a, const uint32_t* b) {
    asm volatile(
        "mma.sync.aligned.m16n8k16.row.col.f32.f16.f16.f32 "
        "{%0,%1,%2,%3}, {%4,%5,%6,%7}, {%8,%9}, {%0,%1,%2,%3};"
        : "+f"(c[0]), "+f"(c[1]), "+f"(c[2]), "+f"(c[3])
        : "r"(a[0]), "r"(a[1]), "r"(a[2]), "r"(a[3]), "r"(b[0]), "r"(b[1]));
}

// ============================================================================
// Kernel 1: inv_deg[i] = 1/rowsum(A[i,:]); also emits fp16 copy of A. [R11]
// ============================================================================
__global__ void __launch_bounds__(256) rowsum_kernel(const float* __restrict__ A) {
    int row = blockIdx.x;
    const float4* r4 = reinterpret_cast<const float4*>(A + (size_t)row * NN);
    __half* ah = g_Ah + (size_t)row * NN;
    float s = 0.f;
#pragma unroll
    for (int it = 0; it < (NN / 4) / 256; it++) {
        int idx = it * 256 + threadIdx.x;
        float4 v = r4[idx];
        s += (v.x + v.y) + (v.z + v.w);
        union { __half2 h[2]; uint2 u; } p;
        p.h[0] = __floats2half2_rn(v.x, v.y);
        p.h[1] = __floats2half2_rn(v.z, v.w);
        *reinterpret_cast<uint2*>(ah + (size_t)idx * 4) = p.u;
    }
    __shared__ float red[256];
    red[threadIdx.x] = s;
    __syncthreads();
#pragma unroll
    for (int o = 128; o > 0; o >>= 1) {
        if (threadIdx.x < o) red[threadIdx.x] += red[threadIdx.x + o];
        __syncthreads();
    }
    if (threadIdx.x == 0) g_inv_deg[row] = 1.0f / red[0];
}

// ============================================================================
// Kernel 2 (tensor-core): ysTh[d][j] = fp16( YSCALE*inv_j * sum_k W[k][d] x[j][k] )
// [R11, unchanged — measured ~7us]
// ============================================================================
constexpr int XROWW = (128 + 8) * 2;
constexpr int XROWX = (64 + 8) * 2;
constexpr int XW_TILE_W = 64 * XROWW;
constexpr int XW_TILE_X = 128 * XROWX;
constexpr int SMEM_XW = XW_TILE_W + XW_TILE_X + 128 * 4 + 256;

__global__ void __launch_bounds__(512, 1) xw_tensor_kernel(const float* __restrict__ x,
                                                           const float* __restrict__ W) {
    extern __shared__ char smem[];
    const uint32_t sW = smem_u32(smem);
    const uint32_t sX = sW + XW_TILE_W;
    float* ivd = reinterpret_cast<float*>(smem + XW_TILE_W + XW_TILE_X);

    const int tid  = threadIdx.x;
    const int wid  = tid >> 5;
    const int lane = tid & 31;
    const int wm   = wid >> 2;
    const int wn   = wid & 3;
    const int jbase = blockIdx.x * 128;
    const int dbase = blockIdx.y * 128;

    if (tid < 128) ivd[tid] = g_inv_deg[jbase + tid] * YSCALE;

    const int g2 = lane >> 2, t2 = lane & 3;
    const int q = lane >> 3, r = lane & 7;
    const uint32_t boff = (uint32_t)((wn * 32 + (q >> 1) * 8 + r) * XROWX + (q & 1) * 16);

    float4 regW[4], regX[4];
    auto ldgW = [&](int kt) {
        const int k0 = kt * 64;
#pragma unroll
        for (int i = 0; i < 4; i++) {
            int c = i * 512 + tid;
            regW[i] = *reinterpret_cast<const float4*>(
                W + (size_t)(k0 + (c >> 5)) * DF + dbase + (c & 31) * 4);
        }
    };
    auto ldgX = [&](int kt) {
        const int k0 = kt * 64;
#pragma unroll
        for (int i = 0; i < 4; i++) {
            int c = i * 512 + tid;
            regX[i] = *reinterpret_cast<const float4*>(
                x + (size_t)(jbase + (c >> 4)) * DF + k0 + (c & 15) * 4);
        }
    };
    auto stsAll = [&]() {
#pragma unroll
        for (int i = 0; i < 4; i++) {
            int c = i * 512 + tid;
            union { __half2 h[2]; uint2 u; } p;
            p.h[0] = __floats2half2_rn(regW[i].x, regW[i].y);
            p.h[1] = __floats2half2_rn(regW[i].z, regW[i].w);
            asm volatile("st.shared.v2.u32 [%0], {%1,%2};"
                         :: "r"(sW + (c >> 5) * XROWW + (c & 31) * 8),
                            "r"(p.u.x), "r"(p.u.y) : "memory");
            union { __half2 h[2]; uint2 u; } px;
            px.h[0] = __floats2half2_rn(regX[i].x, regX[i].y);
            px.h[1] = __floats2half2_rn(regX[i].z, regX[i].w);
            asm volatile("st.shared.v2.u32 [%0], {%1,%2};"
                         :: "r"(sX + (c >> 4) * XROWX + (c & 15) * 8),
                            "r"(px.u.x), "r"(px.u.y) : "memory");
        }
    };

    float acc[2][4][4];
#pragma unroll
    for (int mt = 0; mt < 2; mt++)
#pragma unroll
        for (int nt = 0; nt < 4; nt++)
#pragma unroll
            for (int i = 0; i < 4; i++) acc[mt][nt][i] = 0.f;

    ldgW(0); ldgX(0);
    for (int kt = 0; kt < 4; kt++) {
        __syncthreads();
        stsAll();
        if (kt + 1 < 4) { ldgW(kt + 1); ldgX(kt + 1); }
        __syncthreads();
#pragma unroll
        for (int ks = 0; ks < 4; ks++) {
            uint32_t afr[2][4];
#pragma unroll
            for (int mt = 0; mt < 2; mt++) {
                uint32_t ap = sW + (uint32_t)((ks * 16 + (q >> 1) * 8 + r) * XROWW
                              + (wm * 32 + mt * 16 + (q & 1) * 8) * 2);
                ldsm4t(afr[mt], ap);
            }
            uint32_t bfr[2][4];
#pragma unroll
            for (int np = 0; np < 2; np++)
                ldsm4(bfr[np], sX + boff + np * (16 * XROWX) + ks * 32);
#pragma unroll
            for (int mt = 0; mt < 2; mt++)
#pragma unroll
                for (int nt = 0; nt < 4; nt++)
                    mma_f16(acc[mt][nt], afr[mt], &bfr[nt >> 1][(nt & 1) * 2]);
        }
    }

#pragma unroll
    for (int mt = 0; mt < 2; mt++) {
        const int d0 = dbase + wm * 32 + mt * 16 + g2;
#pragma unroll
        for (int nt = 0; nt < 4; nt++) {
            const int cl = wn * 32 + nt * 8 + t2 * 2;
            const float v0 = ivd[cl], v1 = ivd[cl + 1];
            union { __half2 h; uint32_t u; } p0, p1;
            p0.h = __floats2half2_rn(acc[mt][nt][0] * v0, acc[mt][nt][1] * v1);
            p1.h = __floats2half2_rn(acc[mt][nt][2] * v0, acc[mt][nt][3] * v1);
            *reinterpret_cast<uint32_t*>(&g_ysTh[(size_t)d0 * NN + jbase + cl]) = p0.u;
            *reinterpret_cast<uint32_t*>(&g_ysTh[(size_t)(d0 + 8) * NN + jbase + cl]) = p1.u;
        }
    }
}

// ============================================================================
// Kernel 3: out = relu( (inv_deg_i/YSCALE) * (Ah @ Yh) + bias )
// OCCUPANCY FIX: 2 CTAs/SM. Tile BM=128 x BN=64, BK=64, 256 threads (8 warps,
// warp grid 4x2, warp tile 32x32), 3-stage cp.async. Grid 64x4 = 256 CTAs.
// Independent per-CTA barriers keep the tensor pipe fed (R15: tensor=41.7%).
// ============================================================================
constexpr int BM = 128, BN = 64, BK = 64;
constexpr int STAGES = 3;
constexpr int NK = NN / BK;                   // 128
constexpr int ROWH = (BK + 8) * 2;            // 144
constexpr int A_TILE = BM * ROWH;             // 18432
constexpr int B_TILE = BN * ROWH;             // 9216
constexpr int STAGE_B = A_TILE + B_TILE;      // 27648
constexpr int SMEM_GEMM = STAGES * STAGE_B + (BM + BN) * 4;   // 83712

__global__ void __launch_bounds__(256, 2) gcn_gemm_kernel(const float* __restrict__ bias,
                                                          float* __restrict__ out) {
    extern __shared__ char smem[];
    const uint32_t sbase = smem_u32(smem);
    float* invd_s = reinterpret_cast<float*>(smem + STAGES * STAGE_B);
    float* bias_s = invd_s + BM;

    const int tid  = threadIdx.x;
    const int wid  = tid >> 5;
    const int lane = tid & 31;
    const int wm   = wid >> 1;          // 0..3 : 32-row slab
    const int wn   = wid & 1;           // 0..1 : 32-col slab
    const int mbase = blockIdx.x * BM;
    const int nbase = blockIdx.y * BN;

    if (tid < BM) invd_s[tid] = g_inv_deg[mbase + tid] * (1.0f / YSCALE);
    if (tid < BN) bias_s[tid] = bias[nbase + tid];

    const int g2 = lane >> 2, t2 = lane & 3;
    const int q = lane >> 3, r = lane & 7;
    const uint32_t aoff = (uint32_t)((wm * 32 + (q & 1) * 8 + r) * ROWH + (q >> 1) * 16);
    const uint32_t boff = (uint32_t)((wn * 32 + (q >> 1) * 8 + r) * ROWH + (q & 1) * 16);

    // stage loader: A 1024 + B 512 fp16 16B chunks over 256 threads (6 each)
    auto load_stage = [&](int st, int kt) {
        const uint32_t sA = sbase + st * STAGE_B;
        const uint32_t sB = sA + A_TILE;
        const int k0 = kt * BK;
#pragma unroll
        for (int i = 0; i < 6; i++) {
            int c = i * 256 + tid;            // 0..1535
            if (c < 1024) {
                int row = c >> 3, cq = c & 7;
                cp16(sA + row * ROWH + cq * 16,
                     g_Ah + (size_t)(mbase + row) * NN + k0 + cq * 8);
            } else {
                int c2 = c - 1024;
                int row = c2 >> 3, cq = c2 & 7;
                cp16(sB + row * ROWH + cq * 16,
                     g_ysTh + (size_t)(nbase + row) * NN + k0 + cq * 8);
            }
        }
    };

    float acc[2][4][4];
#pragma unroll
    for (int mt = 0; mt < 2; mt++)
#pragma unroll
        for (int nt = 0; nt < 4; nt++)
#pragma unroll
            for (int i = 0; i < 4; i++) acc[mt][nt][i] = 0.f;

    load_stage(0, 0); cp_commit();
    load_stage(1, 1); cp_commit();

    int st = 0;
    for (int kt = 0; kt < NK; kt++) {
        cp_wait<1>();
        __syncthreads();

        int pst = st + 2 >= STAGES ? st + 2 - STAGES : st + 2;
        if (kt + 2 < NK) load_stage(pst, kt + 2);
        cp_commit();

        const uint32_t sA = sbase + st * STAGE_B;
        const uint32_t sB = sA + A_TILE;
#pragma unroll
        for (int ks = 0; ks < 4; ks++) {       // 4 x k16 steps
            uint32_t afr[2][4];
#pragma unroll
            for (int mt = 0; mt < 2; mt++)
                ldsm4(afr[mt], sA + aoff + mt * (16 * ROWH) + ks * 32);
            uint32_t bfr[2][4];
#pragma unroll
            for (int np = 0; np < 2; np++)
                ldsm4(bfr[np], sB + boff + np * (16 * ROWH) + ks * 32);
#pragma unroll
            for (int mt = 0; mt < 2; mt++)
#pragma unroll
                for (int nt = 0; nt < 4; nt++)
                    mma_f16(acc[mt][nt], afr[mt], &bfr[nt >> 1][(nt & 1) * 2]);
        }
        st = st + 1 >= STAGES ? 0 : st + 1;
    }

    // epilogue: scale by inv_deg(row)/YSCALE, add bias, relu, store float2
#pragma unroll
    for (int mt = 0; mt < 2; mt++) {
        const int rl = wm * 32 + mt * 16 + g2;
        const float s0 = invd_s[rl], s1 = invd_s[rl + 8];
        float* o0 = out + (size_t)(mbase + rl) * DF + nbase + wn * 32;
        float* o1 = o0 + (size_t)8 * DF;
#pragma unroll
        for (int nt = 0; nt < 4; nt++) {
            const int c = nt * 8 + t2 * 2;
            const float b0 = bias_s[wn * 32 + c], b1 = bias_s[wn * 32 + c + 1];
            float2 v0, v1;
            v0.x = fmaxf(fmaf(acc[mt][nt][0], s0, b0), 0.f);
            v0.y = fmaxf(fmaf(acc[mt][nt][1], s0, b1), 0.f);
            v1.x = fmaxf(fmaf(acc[mt][nt][2], s1, b0), 0.f);
            v1.y = fmaxf(fmaf(acc[mt][nt][3], s1, b1), 0.f);
            *reinterpret_cast<float2*>(o0 + c) = v0;
            *reinterpret_cast<float2*>(o1 + c) = v1;
        }
    }
}

// ============================================================================
// Launch
// ============================================================================
extern "C" void kernel_launch(void* const* d_in, const int* in_sizes, int n_in,
                              void* d_out, int out_size) {
    const float* x    = (const float*)d_in[0];   // [8192,256]
    const float* adj  = (const float*)d_in[1];   // [8192,8192]
    const float* W    = (const float*)d_in[2];   // [256,256]
    const float* bias = (const float*)d_in[3];   // [256]
    float* out = (float*)d_out;                  // [8192,256]

    cudaFuncSetAttribute(gcn_gemm_kernel, cudaFuncAttributeMaxDynamicSharedMemorySize,
                         SMEM_GEMM);
    cudaFuncSetAttribute(xw_tensor_kernel, cudaFuncAttributeMaxDynamicSharedMemorySize,
                         SMEM_XW);

    rowsum_kernel<<<NN, 256>>>(adj);
    dim3 xgrid(NN / 128, DF / 128);   // 64 x 2
    xw_tensor_kernel<<<xgrid, 512, SMEM_XW>>>(x, W);
    dim3 grid(NN / BM, DF / BN);      // 64 x 4 = 256 CTAs, 2 per SM
    gcn_gemm_kernel<<<grid, 256, SMEM_GEMM>>>(bias, out);
}

// round 17
// speedup vs baseline: 1.0100x; 1.0100x over previous
#include <cuda_runtime.h>
#include <cuda_fp16.h>
#include <cstdint>

#define DEV_INLINE __device__ __forceinline__

constexpr int NN = 8192;   // nodes
constexpr int DF = 256;    // feature dim
constexpr float YSCALE = 4096.f;   // exact pow2: keeps Y out of fp16 subnormals
constexpr int NSM = 148;           // persistent CTA count

// span partition: CTA c owns global iters [c*16384/148, (c+1)*16384/148)
constexpr int span_start_h(int c) { return (c * 4096) / 37; }
DEV_INLINE int span_start(int c) { return (c * 4096) / 37; }

// total flush events across all CTAs (boundary flush or span-end flush)
constexpr unsigned total_flushes() {
    unsigned n = 0;
    for (int c = 0; c < NSM; c++) {
        int s = span_start_h(c), e = span_start_h(c + 1);
        for (int gi = s; gi < e; gi++)
            if ((gi & 127) == 127 || gi == e - 1) n++;
    }
    return n;
}
constexpr unsigned TOTAL_FLUSHES = total_flushes();

// ---------------- intermediates (static device globals; no runtime alloc) ----
__device__ float    g_inv_deg[NN];
__device__ __half   g_Ah[(size_t)NN * NN];     // fp16 copy of adjacency (rn)
__device__ __half   g_ysTh[(size_t)DF * NN];   // [d][j] = fp16( YSCALE*inv_j*(xW)[j][d] )
__device__ float    g_part[NSM][2][128 * 128]; // per-CTA raw partial tiles
__device__ unsigned g_total;                   // global flush counter

// ============================================================================
// helpers (baseline sm_103 ISA only: cp.async, ldmatrix, mma.sync)
// ============================================================================
DEV_INLINE uint32_t smem_u32(const void* p) {
    uint32_t a;
    asm("{ .reg .u64 t; cvta.to.shared.u64 t, %1; cvt.u32.u64 %0, t; }" : "=r"(a) : "l"(p));
    return a;
}
DEV_INLINE void cp16(uint32_t saddr, const void* g) {
    asm volatile("cp.async.cg.shared.global [%0], [%1], 16;" :: "r"(saddr), "l"(g));
}
DEV_INLINE void cp_commit() { asm volatile("cp.async.commit_group;"); }
template <int N> DEV_INLINE void cp_wait() { asm volatile("cp.async.wait_group %0;" :: "n"(N)); }

DEV_INLINE void ldsm4(uint32_t* d, uint32_t addr) {
    asm volatile("ldmatrix.sync.aligned.m8n8.x4.shared.b16 {%0,%1,%2,%3}, [%4];"
                 : "=r"(d[0]), "=r"(d[1]), "=r"(d[2]), "=r"(d[3]) : "r"(addr));
}
DEV_INLINE void ldsm4t(uint32_t* d, uint32_t addr) {
    asm volatile("ldmatrix.sync.aligned.m8n8.x4.trans.shared.b16 {%0,%1,%2,%3}, [%4];"
                 : "=r"(d[0]), "=r"(d[1]), "=r"(d[2]), "=r"(d[3]) : "r"(addr));
}
DEV_INLINE void mma_f16(float* c, const uint32_t* a, const uint32_t* b) {
    asm volatile(
        "mma.sync.aligned.m16n8k16.row.col.f32.f16.f16.f32 "
        "{%0,%1,%2,%3}, {%4,%5,%6,%7}, {%8,%9}, {%0,%1,%2,%3};"
        : "+f"(c[0]), "+f"(c[1]), "+f"(c[2]), "+f"(c[3])
        : "r"(a[0]), "r"(a[1]), "r"(a[2]), "r"(a[3]), "r"(b[0]), "r"(b[1]));
}

// ============================================================================
// Kernel 1: inv_deg[i] = 1/rowsum(A[i,:]); emits fp16 A; resets flush counter.
// ============================================================================
__global__ void __launch_bounds__(256) rowsum_kernel(const float* __restrict__ A) {
    if (blockIdx.x == 0 && threadIdx.x == 0) g_total = 0u;

    int row = blockIdx.x;
    const float4* r4 = reinterpret_cast<const float4*>(A + (size_t)row * NN);
    __half* ah = g_Ah + (size_t)row * NN;
    float s = 0.f;
#pragma unroll
    for (int it = 0; it < (NN / 4) / 256; it++) {
        int idx = it * 256 + threadIdx.x;
        float4 v = r4[idx];
        s += (v.x + v.y) + (v.z + v.w);
        union { __half2 h[2]; uint2 u; } p;
        p.h[0] = __floats2half2_rn(v.x, v.y);
        p.h[1] = __floats2half2_rn(v.z, v.w);
        *reinterpret_cast<uint2*>(ah + (size_t)idx * 4) = p.u;
    }
    __shared__ float red[256];
    red[threadIdx.x] = s;
    __syncthreads();
#pragma unroll
    for (int o = 128; o > 0; o >>= 1) {
        if (threadIdx.x < o) red[threadIdx.x] += red[threadIdx.x + o];
        __syncthreads();
    }
    if (threadIdx.x == 0) g_inv_deg[row] = 1.0f / red[0];
}

// ============================================================================
// Kernel 2 (tensor-core): ysTh[d][j] = fp16( YSCALE*inv_j * sum_k W[k][d] x[j][k] )
// [R11, unchanged — measured ~7us]
// ============================================================================
constexpr int XROWW = (128 + 8) * 2;
constexpr int XROWX = (64 + 8) * 2;
constexpr int XW_TILE_W = 64 * XROWW;
constexpr int XW_TILE_X = 128 * XROWX;
constexpr int SMEM_XW = XW_TILE_W + XW_TILE_X + 128 * 4 + 256;

__global__ void __launch_bounds__(512, 1) xw_tensor_kernel(const float* __restrict__ x,
                                                           const float* __restrict__ W) {
    extern __shared__ char smem[];
    const uint32_t sW = smem_u32(smem);
    const uint32_t sX = sW + XW_TILE_W;
    float* ivd = reinterpret_cast<float*>(smem + XW_TILE_W + XW_TILE_X);

    const int tid  = threadIdx.x;
    const int wid  = tid >> 5;
    const int lane = tid & 31;
    const int wm   = wid >> 2;
    const int wn   = wid & 3;
    const int jbase = blockIdx.x * 128;
    const int dbase = blockIdx.y * 128;

    if (tid < 128) ivd[tid] = g_inv_deg[jbase + tid] * YSCALE;

    const int g2 = lane >> 2, t2 = lane & 3;
    const int q = lane >> 3, r = lane & 7;
    const uint32_t boff = (uint32_t)((wn * 32 + (q >> 1) * 8 + r) * XROWX + (q & 1) * 16);

    float4 regW[4], regX[4];
    auto ldgW = [&](int kt) {
        const int k0 = kt * 64;
#pragma unroll
        for (int i = 0; i < 4; i++) {
            int c = i * 512 + tid;
            regW[i] = *reinterpret_cast<const float4*>(
                W + (size_t)(k0 + (c >> 5)) * DF + dbase + (c & 31) * 4);
        }
    };
    auto ldgX = [&](int kt) {
        const int k0 = kt * 64;
#pragma unroll
        for (int i = 0; i < 4; i++) {
            int c = i * 512 + tid;
            regX[i] = *reinterpret_cast<const float4*>(
                x + (size_t)(jbase + (c >> 4)) * DF + k0 + (c & 15) * 4);
        }
    };
    auto stsAll = [&]() {
#pragma unroll
        for (int i = 0; i < 4; i++) {
            int c = i * 512 + tid;
            union { __half2 h[2]; uint2 u; } p;
            p.h[0] = __floats2half2_rn(regW[i].x, regW[i].y);
            p.h[1] = __floats2half2_rn(regW[i].z, regW[i].w);
            asm volatile("st.shared.v2.u32 [%0], {%1,%2};"
                         :: "r"(sW + (c >> 5) * XROWW + (c & 31) * 8),
                            "r"(p.u.x), "r"(p.u.y) : "memory");
            union { __half2 h[2]; uint2 u; } px;
            px.h[0] = __floats2half2_rn(regX[i].x, regX[i].y);
            px.h[1] = __floats2half2_rn(regX[i].z, regX[i].w);
            asm volatile("st.shared.v2.u32 [%0], {%1,%2};"
                         :: "r"(sX + (c >> 4) * XROWX + (c & 15) * 8),
                            "r"(px.u.x), "r"(px.u.y) : "memory");
        }
    };

    float acc[2][4][4];
#pragma unroll
    for (int mt = 0; mt < 2; mt++)
#pragma unroll
        for (int nt = 0; nt < 4; nt++)
#pragma unroll
            for (int i = 0; i < 4; i++) acc[mt][nt][i] = 0.f;

    ldgW(0); ldgX(0);
    for (int kt = 0; kt < 4; kt++) {
        __syncthreads();
        stsAll();
        if (kt + 1 < 4) { ldgW(kt + 1); ldgX(kt + 1); }
        __syncthreads();
#pragma unroll
        for (int ks = 0; ks < 4; ks++) {
            uint32_t afr[2][4];
#pragma unroll
            for (int mt = 0; mt < 2; mt++) {
                uint32_t ap = sW + (uint32_t)((ks * 16 + (q >> 1) * 8 + r) * XROWW
                              + (wm * 32 + mt * 16 + (q & 1) * 8) * 2);
                ldsm4t(afr[mt], ap);
            }
            uint32_t bfr[2][4];
#pragma unroll
            for (int np = 0; np < 2; np++)
                ldsm4(bfr[np], sX + boff + np * (16 * XROWX) + ks * 32);
#pragma unroll
            for (int mt = 0; mt < 2; mt++)
#pragma unroll
                for (int nt = 0; nt < 4; nt++)
                    mma_f16(acc[mt][nt], afr[mt], &bfr[nt >> 1][(nt & 1) * 2]);
        }
    }

#pragma unroll
    for (int mt = 0; mt < 2; mt++) {
        const int d0 = dbase + wm * 32 + mt * 16 + g2;
#pragma unroll
        for (int nt = 0; nt < 4; nt++) {
            const int cl = wn * 32 + nt * 8 + t2 * 2;
            const float v0 = ivd[cl], v1 = ivd[cl + 1];
            union { __half2 h; uint32_t u; } p0, p1;
            p0.h = __floats2half2_rn(acc[mt][nt][0] * v0, acc[mt][nt][1] * v1);
            p1.h = __floats2half2_rn(acc[mt][nt][2] * v0, acc[mt][nt][3] * v1);
            *reinterpret_cast<uint32_t*>(&g_ysTh[(size_t)d0 * NN + jbase + cl]) = p0.u;
            *reinterpret_cast<uint32_t*>(&g_ysTh[(size_t)(d0 + 8) * NN + jbase + cl]) = p1.u;
        }
    }
}

// ============================================================================
// Kernel 3: persistent span GEMM + FLAT fused reduce (all 148 CTAs).
// Mainloop: span over flattened (tile,k) space, flush raw fp32 partials,
// bump global counter. Tail: spin on counter==TOTAL_FLUSHES (all CTAs finish
// ~simultaneously), then flat-partition the 2M-element reduce + epilogue
// across 148 CTAs x 512 threads. Fixed ascending-cc sum order -> determinism.
// ============================================================================
constexpr int BK = 64;
constexpr int ROWH = (BK + 8) * 2;            // 144
constexpr int TILE_B = 128 * ROWH;            // 18432
constexpr int STAGE_B = 2 * TILE_B;           // 36864
constexpr int STAGES = 3;
constexpr int SMEM_GEMM = STAGES * STAGE_B;   // 110592
constexpr int TOT_F4 = 128 * 4096;            // total float4 work items (2M floats)
constexpr int CHUNK_F4 = (TOT_F4 + NSM - 1) / NSM;   // 3543

__global__ void __launch_bounds__(512, 1) gcn_gemm_kernel(const float* __restrict__ bias,
                                                          float* __restrict__ out) {
    extern __shared__ char smem[];
    const uint32_t sbase = smem_u32(smem);

    const int tid  = threadIdx.x;
    const int wid  = tid >> 5;
    const int lane = tid & 31;
    const int wm   = wid >> 2;
    const int wn   = wid & 3;
    const int cta  = blockIdx.x;

    const int start = span_start(cta);
    const int end   = span_start(cta + 1);

    const int g2 = lane >> 2, t2 = lane & 3;
    const int q = lane >> 3, r = lane & 7;
    const uint32_t aoff = (uint32_t)((wm * 32 + (q & 1) * 8 + r) * ROWH + (q >> 1) * 16);
    const uint32_t boff = (uint32_t)((wn * 32 + (q >> 1) * 8 + r) * ROWH + (q & 1) * 16);

    auto load_stage = [&](int st, int gi) {
        const int tile = gi >> 7, kit = gi & 127;
        const int mb = (tile >> 1) * 128, nb = (tile & 1) * 128, k0 = kit * BK;
        const uint32_t sA = sbase + st * STAGE_B;
        const uint32_t sB = sA + TILE_B;
#pragma unroll
        for (int i = 0; i < 4; i++) {
            int c = i * 512 + tid;            // 0..2047
            if (c < 1024) {
                int row = c >> 3, cq = c & 7;
                cp16(sA + row * ROWH + cq * 16,
                     g_Ah + (size_t)(mb + row) * NN + k0 + cq * 8);
            } else {
                int c2 = c - 1024;
                int row = c2 >> 3, cq = c2 & 7;
                cp16(sB + row * ROWH + cq * 16,
                     g_ysTh + (size_t)(nb + row) * NN + k0 + cq * 8);
            }
        }
    };

    float acc[2][4][4];
#pragma unroll
    for (int mt = 0; mt < 2; mt++)
#pragma unroll
        for (int nt = 0; nt < 4; nt++)
#pragma unroll
            for (int i = 0; i < 4; i++) acc[mt][nt][i] = 0.f;

    load_stage(0, start); cp_commit();
    load_stage(1, start + 1); cp_commit();

    int st = 0, seg = 0;
    for (int gi = start; gi < end; gi++) {
        cp_wait<1>();
        __syncthreads();

        int pst = st + 2 >= STAGES ? st + 2 - STAGES : st + 2;
        if (gi + 2 < end) load_stage(pst, gi + 2);
        cp_commit();

        const uint32_t sA = sbase + st * STAGE_B;
        const uint32_t sB = sA + TILE_B;
#pragma unroll
        for (int ks = 0; ks < 4; ks++) {
            uint32_t afr[2][4];
#pragma unroll
            for (int mt = 0; mt < 2; mt++)
                ldsm4(afr[mt], sA + aoff + mt * (16 * ROWH) + ks * 32);
            uint32_t bfr[2][4];
#pragma unroll
            for (int np = 0; np < 2; np++)
                ldsm4(bfr[np], sB + boff + np * (16 * ROWH) + ks * 32);
#pragma unroll
            for (int mt = 0; mt < 2; mt++)
#pragma unroll
                for (int nt = 0; nt < 4; nt++)
                    mma_f16(acc[mt][nt], afr[mt], &bfr[nt >> 1][(nt & 1) * 2]);
        }

        // --- flush raw partial tile + global counter bump (uniform branch)
        if ((gi & 127) == 127 || gi == end - 1) {
            float* p = &g_part[cta][seg][0];
#pragma unroll
            for (int mt = 0; mt < 2; mt++) {
                const int rl = wm * 32 + mt * 16 + g2;
#pragma unroll
                for (int nt = 0; nt < 4; nt++) {
                    const int col = wn * 32 + nt * 8 + t2 * 2;
                    *reinterpret_cast<float2*>(p + rl * 128 + col) =
                        make_float2(acc[mt][nt][0], acc[mt][nt][1]);
                    *reinterpret_cast<float2*>(p + (rl + 8) * 128 + col) =
                        make_float2(acc[mt][nt][2], acc[mt][nt][3]);
#pragma unroll
                    for (int i = 0; i < 4; i++) acc[mt][nt][i] = 0.f;
                }
            }
            seg = 1;
            __syncthreads();                 // all partial stores issued
            if (tid == 0) {
                __threadfence();             // publish partials
                atomicAdd(&g_total, 1u);
            }
        }
        st = st + 1 >= STAGES ? 0 : st + 1;
    }

    // ---------------- flat fused reduce + epilogue over all 148 CTAs --------
    if (tid == 0) {
        while (atomicAdd(&g_total, 0u) < TOTAL_FLUSHES) __nanosleep(100);
    }
    __syncthreads();
    __threadfence();                         // acquire all partials

    const int f0 = cta * CHUNK_F4;
    const int f1 = (f0 + CHUNK_F4 < TOT_F4) ? f0 + CHUNK_F4 : TOT_F4;
    for (int f = f0 + tid; f < f1; f += 512) {
        const int t = f >> 12;               // tile (4096 float4 per tile)
        const int e = (f & 4095) * 4;        // element offset within tile
        const int row = e >> 7, col = e & 127;
        const int lo = t << 7, hi = lo + 127;

        float4 s = make_float4(0.f, 0.f, 0.f, 0.f);
        int cc = (lo * NSM) >> 14; if (cc > 0) cc--;
        for (; cc < NSM; cc++) {
            const int cs = span_start(cc);
            if (cs > hi) break;
            if (span_start(cc + 1) > lo) {
                const float* p = &g_part[cc][(t == (cs >> 7)) ? 0 : 1][0];
                const float4 pv = *reinterpret_cast<const float4*>(p + e);
                s.x += pv.x; s.y += pv.y; s.z += pv.z; s.w += pv.w;
            }
        }
        const int mb = (t >> 1) * 128, nb = (t & 1) * 128;
        const float sinv = g_inv_deg[mb + row] * (1.0f / YSCALE);
        const float4 b = *reinterpret_cast<const float4*>(bias + nb + col);
        float4 o;
        o.x = fmaxf(fmaf(s.x, sinv, b.x), 0.f);
        o.y = fmaxf(fmaf(s.y, sinv, b.y), 0.f);
        o.z = fmaxf(fmaf(s.z, sinv, b.z), 0.f);
        o.w = fmaxf(fmaf(s.w, sinv, b.w), 0.f);
        *reinterpret_cast<float4*>(out + (size_t)(mb + row) * DF + nb + col) = o;
    }
}

// ============================================================================
// Launch
// ============================================================================
extern "C" void kernel_launch(void* const* d_in, const int* in_sizes, int n_in,
                              void* d_out, int out_size) {
    const float* x    = (const float*)d_in[0];   // [8192,256]
    const float* adj  = (const float*)d_in[1];   // [8192,8192]
    const float* W    = (const float*)d_in[2];   // [256,256]
    const float* bias = (const float*)d_in[3];   // [256]
    float* out = (float*)d_out;                  // [8192,256]

    cudaFuncSetAttribute(gcn_gemm_kernel, cudaFuncAttributeMaxDynamicSharedMemorySize,
                         SMEM_GEMM);
    cudaFuncSetAttribute(xw_tensor_kernel, cudaFuncAttributeMaxDynamicSharedMemorySize,
                         SMEM_XW);

    rowsum_kernel<<<NN, 256>>>(adj);
    dim3 xgrid(NN / 128, DF / 128);   // 64 x 2
    xw_tensor_kernel<<<xgrid, 512, SMEM_XW>>>(x, W);
    gcn_gemm_kernel<<<NSM, 512, SMEM_GEMM>>>(bias, out);
}